// round 14
// baseline (speedup 1.0000x reference)
#include <cuda_runtime.h>
#include <cuda_bf16.h>
#include <math.h>
#include <stdint.h>

#define NIN   1024
#define KDIM  1024
#define EDIM  256
#define BM    32
#define NPAIRS 1024
#define ASLAB 1024                     // 32 rows x 32B bf16 per kchunk (16 k)
#define WSLAB 32768                    // 1024 ko x 32B bf16 per kchunk
#define ASTG  (2 * ASLAB)              // 2 kchunks per stage
#define WSTG  (2 * WSLAB)
#define STAGE (ASTG + WSTG)            // 67584
#define NSTAGE 3
#define SMEM_DYN (NSTAGE * STAGE)      // 202752
#define NTHREADS 512
#define NWARP 16
#define ITERS_PER_TILE 32
#define MARGIN 0.03f

// ---------------- device scratch ----------------
__device__ __align__(128) unsigned char g_xs[(size_t)2048 * 64 * ASLAB];  // 134MB
__device__ __align__(128) unsigned char g_ws[(size_t)64 * WSLAB];         // 2MB
__device__ float g_avgp[KDIM];
__device__ unsigned int g_count;

// ---------------- PTX helpers ----------------
__device__ __forceinline__ uint32_t smem_u32(const void* p) {
    uint32_t a;
    asm("{ .reg .u64 t; cvta.to.shared.u64 t, %1; cvt.u32.u64 %0, t; }" : "=r"(a) : "l"(p));
    return a;
}
__device__ __forceinline__ uint32_t cluster_rank() {
    uint32_t r; asm("mov.u32 %0, %%cluster_ctarank;" : "=r"(r)); return r;
}
#define MBAR_INIT(a, n) \
    asm volatile("mbarrier.init.shared.b64 [%0], %1;" :: "r"(a), "r"((uint32_t)(n)) : "memory")
#define MBAR_EXPECT_TX(a, b) \
    asm volatile("mbarrier.arrive.expect_tx.shared.b64 _, [%0], %1;" :: "r"(a), "r"((uint32_t)(b)) : "memory")
#define MBAR_ARRIVE_RANK(a, rk) \
    asm volatile("{ .reg .b32 ra; mapa.shared::cluster.u32 ra, %0, %1; " \
                 "mbarrier.arrive.shared::cluster.b64 _, [ra]; }" :: "r"(a), "r"(rk) : "memory")
#define MBAR_WAIT(a, p) do { \
    uint32_t _m = (a); uint32_t _p = (p); uint32_t _d; \
    asm volatile("{\n\t.reg .pred q;\n\tmbarrier.try_wait.parity.acquire.cta.shared::cta.b64 q, [%1], %2;\n\tselp.b32 %0,1,0,q;\n\t}" \
        : "=r"(_d) : "r"(_m), "r"(_p) : "memory"); \
    if (!_d) { \
        asm volatile("{\n\t.reg .pred Q;\n\tWL_%=:\n\tmbarrier.try_wait.parity.acquire.cta.shared::cta.b64 Q, [%0], %1, 0x989680;\n\t@Q bra.uni WD_%=;\n\tbra.uni WL_%=;\n\tWD_%=:\n\t}" \
            :: "r"(_m), "r"(_p) : "memory"); \
    } } while (0)
#define CLUSTER_SYNC() do { \
    asm volatile("barrier.cluster.arrive.aligned;" ::: "memory"); \
    asm volatile("barrier.cluster.wait.aligned;" ::: "memory"); } while (0)

__device__ __forceinline__ void bulk_g2s(uint32_t dst, const void* src, uint32_t bytes, uint32_t mbar) {
    asm volatile("cp.async.bulk.shared::cluster.global.mbarrier::complete_tx::bytes [%0], [%1], %2, [%3];"
        :: "r"(dst), "l"(src), "r"(bytes), "r"(mbar) : "memory");
}
__device__ __forceinline__ void bulk_g2s_mc(uint32_t dst, const void* src, uint32_t bytes, uint32_t mbar, uint16_t mask) {
    asm volatile("cp.async.bulk.shared::cluster.global.mbarrier::complete_tx::bytes.multicast::cluster [%0], [%1], %2, [%3], %4;"
        :: "r"(dst), "l"(src), "r"(bytes), "r"(mbar), "h"(mask) : "memory");
}

__device__ __forceinline__ void mma_bf16(float d[4], uint32_t a0, uint32_t a1, uint32_t a2, uint32_t a3,
                                         uint32_t b0, uint32_t b1) {
    asm volatile(
        "mma.sync.aligned.m16n8k16.row.col.f32.bf16.bf16.f32 "
        "{%0,%1,%2,%3}, {%4,%5,%6,%7}, {%8,%9}, {%0,%1,%2,%3};"
        : "+f"(d[0]), "+f"(d[1]), "+f"(d[2]), "+f"(d[3])
        : "r"(a0), "r"(a1), "r"(a2), "r"(a3), "r"(b0), "r"(b1));
}

__device__ __forceinline__ uint32_t packbf2(float lo, float hi) {
    __nv_bfloat162 h = __floats2bfloat162_rn(lo, hi);
    return *(uint32_t*)&h;
}
// slot s (0..7) holds k-pair c = (s>>1) + (s&1)*4 ;  kperm(c) = (c&3)*2 + (c>>2)
__device__ __forceinline__ int kperm(int c) { return (c & 3) * 2 + (c >> 2); }

// ---------------- merged rearrange: blocks [0,64) do W, [64, 64+B/16) do x ----------------
__global__ __launch_bounds__(512) void rearr_kernel(const float* __restrict__ x,
                                                    const float* __restrict__ W) {
    const int tid = threadIdx.x;
    const int wid = tid >> 5, lane = tid & 31;

    if (blockIdx.x < 64) {
        // ---- W: warp-per-column ----
        const int ko = blockIdx.x * 16 + wid;
        const float4* wr = (const float4*)(W + (size_t)ko * NIN);
        float4 v[8];
        #pragma unroll
        for (int p = 0; p < 8; p++) v[p] = wr[lane + 32 * p];
        #pragma unroll
        for (int p = 0; p < 8; p++) {
            int idx = lane + 32 * p;
            int kchunk = idx >> 2, cc = idx & 3;
            unsigned char* dst = g_ws + (size_t)kchunk * WSLAB + ko * 32;
            *(uint32_t*)(dst + kperm(2 * cc) * 4)     = packbf2(v[p].x, v[p].y);
            *(uint32_t*)(dst + kperm(2 * cc + 1) * 4) = packbf2(v[p].z, v[p].w);
        }
    } else {
        // ---- x: warp-per-row ----
        const int row = (blockIdx.x - 64) * 16 + wid;
        const int rt = row >> 5, rloc = row & 31;
        const float4* xr = (const float4*)(x + (size_t)row * NIN);
        float4 v[8];
        #pragma unroll
        for (int p = 0; p < 8; p++) v[p] = xr[lane + 32 * p];
        unsigned char* base = g_xs + (size_t)rt * 64 * ASLAB;
        #pragma unroll
        for (int p = 0; p < 8; p++) {
            int idx = lane + 32 * p;
            int kchunk = idx >> 2, cc = idx & 3;
            unsigned char* dst = base + (size_t)(kchunk * 32 + rloc) * 32;
            *(uint32_t*)(dst + kperm(2 * cc) * 4)     = packbf2(v[p].x, v[p].y);
            *(uint32_t*)(dst + kperm(2 * cc + 1) * 4) = packbf2(v[p].z, v[p].w);
        }
    }
}

// ---------------- persistent fused bf16 GEMM + epilogue + inline refine ----------------
__global__ __launch_bounds__(NTHREADS, 1) __cluster_dims__(2, 1, 1)
void fused_vq_kernel(const float* __restrict__ x, const float* __restrict__ W,
                     const float* __restrict__ gum, const float* __restrict__ bias,
                     const float* __restrict__ cb, float* __restrict__ out, int B)
{
    extern __shared__ __align__(128) unsigned char smem[];
    __shared__ __align__(8) unsigned long long mb_full[NSTAGE], mb_empty[NSTAGE];
    __shared__ float swmax[NWARP][32];
    __shared__ int   swarg[NWARP][32];
    __shared__ float swsum[NWARP][32];
    __shared__ float frow[32], finv[32];
    __shared__ int   rowcnt[32], srowm[32];
    __shared__ int   rowcols[32][8];
    __shared__ int   s_amblist[32];
    __shared__ int   s_namb;
    __shared__ float sred[NWARP];
    __shared__ int   sIsLast;

    const int tid  = threadIdx.x;
    const int wid  = tid >> 5;
    const int lane = tid & 31;
    const int r0   = lane >> 2;
    const int q    = lane & 3;
    const uint32_t rank = cluster_rank();
    const int cl   = blockIdx.x >> 1;
    const int ncl  = gridDim.x >> 1;
    const int wbase = wid * 64;

    const int ntiles = (NPAIRS - 1 - cl) / ncl + 1;
    const int total_its = ntiles * ITERS_PER_TILE;

    const uint32_t smem_b = smem_u32(smem);
    uint32_t full_a[NSTAGE], empty_a[NSTAGE];
    #pragma unroll
    for (int s = 0; s < NSTAGE; s++) {
        full_a[s]  = smem_u32(&mb_full[s]);
        empty_a[s] = smem_u32(&mb_empty[s]);
    }
    if (tid == 0) {
        #pragma unroll
        for (int s = 0; s < NSTAGE; s++) { MBAR_INIT(full_a[s], 1); MBAR_INIT(empty_a[s], 2); }
    }
    __syncthreads();
    CLUSTER_SYNC();

    const unsigned char* asrc = g_xs + (size_t)(2 * cl + rank) * 64 * ASLAB;

    if (tid == 0) {
        #pragma unroll
        for (int i = 0; i < NSTAGE; i++) {
            MBAR_EXPECT_TX(full_a[i], STAGE);
            bulk_g2s(smem_b + i * STAGE, asrc + (size_t)(2 * i) * ASLAB, ASTG, full_a[i]);
            bulk_g2s_mc(smem_b + i * STAGE + ASTG + rank * WSLAB,
                        g_ws + (size_t)(2 * i + rank) * WSLAB, WSLAB, full_a[i], (uint16_t)0x3);
        }
    }

    int it = 0, s = 0, ph = 0;
    for (int t = 0; t < ntiles; t++) {
        const int p = cl + t * ncl;
        const int rowbase = (2 * p + rank) * BM;

        float f[2][8][4];
        #pragma unroll
        for (int m = 0; m < 2; m++)
            #pragma unroll
            for (int j = 0; j < 8; j++)
                #pragma unroll
                for (int v = 0; v < 4; v++) f[m][j][v] = 0.0f;

        // -------- mainloop: 32 stage-iters x 2 kchunks (R6-proven sync scheme) --------
        for (int g = 0; g < ITERS_PER_TILE; g++) {
            MBAR_WAIT(full_a[s], ph);
            const uint32_t* base = (const uint32_t*)(smem + s * STAGE);
            #pragma unroll
            for (int kc = 0; kc < 2; kc++) {
                const uint32_t* As = base + kc * (ASLAB / 4);
                const uint32_t* Ws = base + (ASTG / 4) + kc * (WSLAB / 4);
                uint2 a[2][2];
                #pragma unroll
                for (int mt = 0; mt < 2; mt++) {
                    a[mt][0] = *(const uint2*)&As[(mt * 16 + r0) * 8 + 2 * q];
                    a[mt][1] = *(const uint2*)&As[(mt * 16 + r0 + 8) * 8 + 2 * q];
                }
                #pragma unroll
                for (int j = 0; j < 8; j++) {
                    uint2 b = *(const uint2*)&Ws[(wbase + j * 8 + r0) * 8 + 2 * q];
                    mma_bf16(f[0][j], a[0][0].x, a[0][1].x, a[0][0].y, a[0][1].y, b.x, b.y);
                    mma_bf16(f[1][j], a[1][0].x, a[1][1].x, a[1][0].y, a[1][1].y, b.x, b.y);
                }
            }
            __syncthreads();
            if (tid == 0) {
                MBAR_ARRIVE_RANK(empty_a[s], 0);
                MBAR_ARRIVE_RANK(empty_a[s], 1);
                const int git = it + NSTAGE;
                if (git < total_its) {
                    const int pi = git / ITERS_PER_TILE, gg = git % ITERS_PER_TILE;
                    const int pp = cl + pi * ncl;
                    MBAR_WAIT(empty_a[s], ph);
                    MBAR_EXPECT_TX(full_a[s], STAGE);
                    bulk_g2s(smem_b + s * STAGE,
                             g_xs + ((size_t)(2 * pp + rank) * 64 + 2 * gg) * ASLAB,
                             ASTG, full_a[s]);
                    bulk_g2s_mc(smem_b + s * STAGE + ASTG + rank * WSLAB,
                                g_ws + (size_t)(2 * gg + rank) * WSLAB, WSLAB,
                                full_a[s], (uint16_t)0x3);
                }
            }
            it++; s++; if (s == NSTAGE) { s = 0; ph ^= 1; }
        }

        // -------- epilogue --------
        // step 1: + bias + gumbel; per-thread row max/arg
        float vmax[4]; int varg[4];
        #pragma unroll
        for (int row_i = 0; row_i < 4; row_i++) {
            const int grow = rowbase + r0 + row_i * 8;
            const int mt = row_i >> 1, hr = row_i & 1;
            float vm = -1e30f; int va = 0;
            #pragma unroll
            for (int j = 0; j < 8; j++) {
                const int col = wbase + j * 8 + 2 * q;
                float2 b2 = *(const float2*)(bias + col);
                float2 g2 = *(const float2*)(gum + (size_t)grow * KDIM + col);
                float v0 = f[mt][j][hr * 2 + 0] + b2.x + g2.x;
                float v1 = f[mt][j][hr * 2 + 1] + b2.y + g2.y;
                f[mt][j][hr * 2 + 0] = v0;
                f[mt][j][hr * 2 + 1] = v1;
                if (v0 > vm) { vm = v0; va = col; }
                if (v1 > vm) { vm = v1; va = col + 1; }
            }
            vmax[row_i] = vm; varg[row_i] = va;
        }
        #pragma unroll
        for (int off = 1; off <= 2; off <<= 1)
            #pragma unroll
            for (int row_i = 0; row_i < 4; row_i++) {
                float ov = __shfl_xor_sync(0xffffffffu, vmax[row_i], off);
                int   oa = __shfl_xor_sync(0xffffffffu, varg[row_i], off);
                if (ov > vmax[row_i] || (ov == vmax[row_i] && oa < varg[row_i])) {
                    vmax[row_i] = ov; varg[row_i] = oa;
                }
            }
        if (q == 0) {
            #pragma unroll
            for (int row_i = 0; row_i < 4; row_i++) {
                swmax[wid][r0 + row_i * 8] = vmax[row_i];
                swarg[wid][r0 + row_i * 8] = varg[row_i];
            }
        }
        __syncthreads();
        if (tid < 32) {
            float best = -1e30f; int barg = KDIM;
            #pragma unroll
            for (int w = 0; w < NWARP; w++) {
                float v = swmax[w][tid]; int a = swarg[w][tid];
                if (v > best || (v == best && a < barg)) { best = v; barg = a; }
            }
            frow[tid] = best; srowm[tid] = barg; rowcnt[tid] = 0;
            if (tid == 0) s_namb = 0;
        }
        __syncthreads();
        // step 3: candidates + exp + row partial sums
        float psum[4] = {0.f, 0.f, 0.f, 0.f};
        #pragma unroll
        for (int row_i = 0; row_i < 4; row_i++) {
            const int row = r0 + row_i * 8;
            const int mt = row_i >> 1, hr = row_i & 1;
            const float rm = frow[row];
            const float th = rm - MARGIN;
            #pragma unroll
            for (int j = 0; j < 8; j++) {
                #pragma unroll
                for (int half = 0; half < 2; half++) {
                    float v = f[mt][j][hr * 2 + half];
                    if (v >= th) {
                        int pos = atomicAdd(&rowcnt[row], 1);
                        if (pos < 8) rowcols[row][pos] = wbase + j * 8 + 2 * q + half;
                    }
                    float e = __expf(v - rm);
                    f[mt][j][hr * 2 + half] = e;
                    psum[row_i] += e;
                }
            }
        }
        #pragma unroll
        for (int off = 1; off <= 2; off <<= 1)
            #pragma unroll
            for (int row_i = 0; row_i < 4; row_i++)
                psum[row_i] += __shfl_xor_sync(0xffffffffu, psum[row_i], off);
        if (q == 0) {
            #pragma unroll
            for (int row_i = 0; row_i < 4; row_i++)
                swsum[wid][r0 + row_i * 8] = psum[row_i];
        }
        __syncthreads();
        if (tid < 32) {
            float sm = 0.0f;
            #pragma unroll
            for (int w = 0; w < NWARP; w++) sm += swsum[w][tid];
            finv[tid] = 1.0f / sm;
            if (rowcnt[tid] > 1) {
                int ix = atomicAdd(&s_namb, 1);
                s_amblist[ix] = tid;
            }
        }
        __syncthreads();
        // step 5: avg_p
        #pragma unroll
        for (int j = 0; j < 8; j++) {
            #pragma unroll
            for (int half = 0; half < 2; half++) {
                float tt = 0.0f;
                #pragma unroll
                for (int row_i = 0; row_i < 4; row_i++) {
                    const int mt = row_i >> 1, hr = row_i & 1;
                    tt += f[mt][j][hr * 2 + half] * finv[r0 + row_i * 8];
                }
                tt += __shfl_xor_sync(0xffffffffu, tt, 4);
                tt += __shfl_xor_sync(0xffffffffu, tt, 8);
                tt += __shfl_xor_sync(0xffffffffu, tt, 16);
                if (r0 == 0) atomicAdd(&g_avgp[wbase + j * 8 + 2 * q + half], tt);
            }
        }
        // step 6: inline fp32 refinement (warp per ambiguous row)
        const int na = s_namb;
        for (int a = wid; a < na; a += NWARP) {
            const int row = s_amblist[a];
            const int nc  = rowcnt[row];
            const int grow = rowbase + row;
            const float* xr = x + (size_t)grow * NIN;
            float best = -1e30f; int bestc = KDIM;
            if (nc <= 8) {
                for (int ti = 0; ti < nc; ti++) {
                    const int c = rowcols[row][ti];
                    const float* wr = W + (size_t)c * NIN;
                    float sm = 0.0f;
                    #pragma unroll 8
                    for (int u = 0; u < 32; u++)
                        sm = fmaf(xr[lane + u * 32], wr[lane + u * 32], sm);
                    #pragma unroll
                    for (int off = 16; off; off >>= 1)
                        sm += __shfl_xor_sync(0xffffffffu, sm, off);
                    float val = sm + bias[c] + gum[(size_t)grow * KDIM + c];
                    if (val > best || (val == best && c < bestc)) { best = val; bestc = c; }
                }
            } else {
                for (int c = 0; c < KDIM; c++) {
                    const float* wr = W + (size_t)c * NIN;
                    float sm = 0.0f;
                    #pragma unroll 8
                    for (int u = 0; u < 32; u++)
                        sm = fmaf(xr[lane + u * 32], wr[lane + u * 32], sm);
                    #pragma unroll
                    for (int off = 16; off; off >>= 1)
                        sm += __shfl_xor_sync(0xffffffffu, sm, off);
                    float val = sm + bias[c] + gum[(size_t)grow * KDIM + c];
                    if (val > best) { best = val; bestc = c; }
                }
            }
            if (lane == 0) srowm[row] = bestc;
        }
        __syncthreads();
        // step 7: m + z_q
        if (tid < 32) out[(size_t)B * EDIM + rowbase + tid] = (float)srowm[tid];
        #pragma unroll
        for (int g2 = 0; g2 < 4; g2++) {
            int idx = g2 * NTHREADS + tid;
            int row = idx >> 6, v = idx & 63;
            int arg = srowm[row];
            float4 cv = *(const float4*)(cb + (size_t)arg * EDIM + v * 4);
            *(float4*)(out + (size_t)(rowbase + row) * EDIM + v * 4) = cv;
        }
        __syncthreads();
    }

    // -------- diversity finisher --------
    __threadfence();
    if (tid == 0) {
        unsigned int old = atomicAdd(&g_count, 1u);
        sIsLast = (old == gridDim.x - 1) ? 1 : 0;
    }
    __syncthreads();
    if (sIsLast) {
        const float invB = 1.0f / (float)B;
        const float logK = logf((float)KDIM);
        float sdiv = 0.0f;
        for (int c = tid; c < KDIM; c += NTHREADS) {
            float p2 = g_avgp[c] * invB;
            sdiv += p2 * (logf(fmaxf(p2, 1e-9f)) + logK);
            g_avgp[c] = 0.0f;
        }
        #pragma unroll
        for (int off = 16; off; off >>= 1)
            sdiv += __shfl_xor_sync(0xffffffffu, sdiv, off);
        if (lane == 0) sred[wid] = sdiv;
        __syncthreads();
        if (tid == 0) {
            float tt = 0.0f;
            #pragma unroll
            for (int w = 0; w < NWARP; w++) tt += sred[w];
            size_t base = (size_t)B * EDIM + B;
            out[base]     = tt;
            out[base + 1] = 0.0f;
            g_count = 0u;
        }
    }
    CLUSTER_SYNC();
}

// ---------------- launch ----------------
extern "C" void kernel_launch(void* const* d_in, const int* in_sizes, int n_in,
                              void* d_out, int out_size) {
    const float* x    = (const float*)d_in[0];
    const float* gum  = (const float*)d_in[1];
    const float* W    = (const float*)d_in[2];
    const float* bias = (const float*)d_in[3];
    const float* cb   = (const float*)d_in[4];
    float* out = (float*)d_out;

    const int B = in_sizes[0] / NIN;             // 65536

    static int nsm = 0;
    if (nsm == 0) {
        cudaDeviceGetAttribute(&nsm, cudaDevAttrMultiProcessorCount, 0);
        nsm &= ~1;
        if (nsm <= 0) nsm = 148;
        cudaFuncSetAttribute(fused_vq_kernel, cudaFuncAttributeMaxDynamicSharedMemorySize, SMEM_DYN);
    }

    rearr_kernel<<<64 + B / 16, 512>>>(x, W);
    fused_vq_kernel<<<nsm, NTHREADS, SMEM_DYN>>>(x, W, gum, bias, cb, out, B);
}